// round 1
// baseline (speedup 1.0000x reference)
#include <cuda_runtime.h>

#define B_ 32
#define L_ 2048
#define D_ 768
#define H_ 512
#define M_ (B_*L_)   // 65536 tokens

// ---- scratch (static __device__ per allocation rules) ----
__device__ float g_h[(size_t)M_ * H_];   // 134 MB intermediate h
__device__ float g_sum[H_];
__device__ float g_sumsq[H_];
__device__ float g_scale[H_];            // istd*gamma
__device__ float g_shift[H_];            // beta - mean*istd*gamma
__device__ float g_counts[B_];           // raw valid counts per batch
__device__ float g_pooled[B_ * H_];      // masked relu-sum before /count

// ---------------------------------------------------------------------------
// 0) zero accumulators
// ---------------------------------------------------------------------------
__global__ void k_zero() {
    int i = blockIdx.x * blockDim.x + threadIdx.x;
    if (i < H_) { g_sum[i] = 0.f; g_sumsq[i] = 0.f; }
    if (i < B_ * H_) g_pooled[i] = 0.f;
}

// ---------------------------------------------------------------------------
// 1) per-batch valid-token counts
// ---------------------------------------------------------------------------
__global__ void k_counts(const int* __restrict__ mask) {
    __shared__ float red[256];
    int b = blockIdx.x;
    float s = 0.f;
    for (int l = threadIdx.x; l < L_; l += 256)
        s += (float)mask[b * L_ + l];
    red[threadIdx.x] = s;
    __syncthreads();
    for (int o = 128; o > 0; o >>= 1) {
        if (threadIdx.x < o) red[threadIdx.x] += red[threadIdx.x + o];
        __syncthreads();
    }
    if (threadIdx.x == 0) g_counts[b] = red[0];
}

// ---------------------------------------------------------------------------
// 2) GEMM1: h = hidden @ W1 + b1    (M=65536, N=512, K=768)
//    BM=128 BN=64 BK=16, 256 threads, 8x4 per thread
// ---------------------------------------------------------------------------
#define BM 128
#define BN 64
#define BK 16
#define TM 8
#define TN 4

__global__ __launch_bounds__(256) void k_gemm1(
    const float* __restrict__ A,   // hidden  (M x K)
    const float* __restrict__ Bw,  // W1      (K x N)
    const float* __restrict__ b1)
{
    __shared__ float As[BK][BM + 4];
    __shared__ float Bs[BK][BN];

    const int t  = threadIdx.x;
    const int tx = t & 15;        // 0..15 -> N
    const int ty = t >> 4;        // 0..15 -> M
    const int m0 = blockIdx.y * BM;
    const int n0 = blockIdx.x * BN;

    float acc[TM][TN];
    #pragma unroll
    for (int i = 0; i < TM; i++)
        #pragma unroll
        for (int j = 0; j < TN; j++) acc[i][j] = 0.f;

    for (int kt = 0; kt < D_; kt += BK) {
        // load A tile (128x16) transposed into As[k][m]
        #pragma unroll
        for (int q = 0; q < 2; q++) {
            int idx = t + q * 256;               // 0..511
            int row = idx >> 2;                  // 0..127
            int kk4 = (idx & 3) << 2;            // 0,4,8,12
            float4 v = *(const float4*)&A[(size_t)(m0 + row) * D_ + kt + kk4];
            As[kk4 + 0][row] = v.x;
            As[kk4 + 1][row] = v.y;
            As[kk4 + 2][row] = v.z;
            As[kk4 + 3][row] = v.w;
        }
        // load B tile (16x64)
        {
            int brow = t >> 4;                   // 0..15
            int bcol = (t & 15) << 2;            // 0..60
            float4 v = *(const float4*)&Bw[(size_t)(kt + brow) * H_ + n0 + bcol];
            *(float4*)&Bs[brow][bcol] = v;
        }
        __syncthreads();

        #pragma unroll
        for (int kk = 0; kk < BK; kk++) {
            float a[TM], b[TN];
            float4 a0 = *(const float4*)&As[kk][ty * TM];
            float4 a1 = *(const float4*)&As[kk][ty * TM + 4];
            a[0]=a0.x; a[1]=a0.y; a[2]=a0.z; a[3]=a0.w;
            a[4]=a1.x; a[5]=a1.y; a[6]=a1.z; a[7]=a1.w;
            float4 bv = *(const float4*)&Bs[kk][tx * TN];
            b[0]=bv.x; b[1]=bv.y; b[2]=bv.z; b[3]=bv.w;
            #pragma unroll
            for (int i = 0; i < TM; i++)
                #pragma unroll
                for (int j = 0; j < TN; j++)
                    acc[i][j] = fmaf(a[i], b[j], acc[i][j]);
        }
        __syncthreads();
    }

    // epilogue: + b1, store h
    float4 b1v = *(const float4*)&b1[n0 + tx * TN];
    #pragma unroll
    for (int i = 0; i < TM; i++) {
        int row = m0 + ty * TM + i;
        float4 o;
        o.x = acc[i][0] + b1v.x;
        o.y = acc[i][1] + b1v.y;
        o.z = acc[i][2] + b1v.z;
        o.w = acc[i][3] + b1v.w;
        *(float4*)&g_h[(size_t)row * H_ + n0 + tx * TN] = o;
    }
}

// ---------------------------------------------------------------------------
// 3) masked per-feature sum / sumsq over h
//    grid 256 blocks x 256 threads; each block handles 256 rows, thread owns
//    cols tid and tid+256. Mask is uniform per row -> no divergence.
// ---------------------------------------------------------------------------
__global__ __launch_bounds__(256) void k_stats(const int* __restrict__ mask) {
    int tid = threadIdx.x;
    int r0 = blockIdx.x * 256;
    float s0 = 0.f, q0 = 0.f, s1 = 0.f, q1 = 0.f;
    for (int r = 0; r < 256; r++) {
        int row = r0 + r;
        if (mask[row]) {
            float v0 = g_h[(size_t)row * H_ + tid];
            float v1 = g_h[(size_t)row * H_ + tid + 256];
            s0 += v0; q0 += v0 * v0;
            s1 += v1; q1 += v1 * v1;
        }
    }
    atomicAdd(&g_sum[tid],         s0);
    atomicAdd(&g_sumsq[tid],       q0);
    atomicAdd(&g_sum[tid + 256],   s1);
    atomicAdd(&g_sumsq[tid + 256], q1);
}

// ---------------------------------------------------------------------------
// 4) finalize BN affine: scale = istd*gamma, shift = beta - mean*scale
// ---------------------------------------------------------------------------
__global__ void k_finalize(const float* __restrict__ gamma,
                           const float* __restrict__ beta) {
    int tid = threadIdx.x;   // 512 threads
    float nv = 0.f;
    #pragma unroll
    for (int b = 0; b < B_; b++) nv += g_counts[b];
    nv = fmaxf(nv, 1.f);
    float mean = g_sum[tid] / nv;
    float var  = g_sumsq[tid] / nv - mean * mean;
    var = fmaxf(var, 0.f);
    float istd = rsqrtf(var + 1e-5f);
    float sc = istd * gamma[tid];
    g_scale[tid] = sc;
    g_shift[tid] = beta[tid] - mean * sc;
}

// ---------------------------------------------------------------------------
// 5) masked relu-normalize-pool: pooled[b][f] += relu(h*scale+shift) for valid
//    grid (8 l-chunks, 32 batches) x 512 threads
// ---------------------------------------------------------------------------
__global__ __launch_bounds__(512) void k_pool(const int* __restrict__ mask) {
    int tid = threadIdx.x;       // feature
    int b = blockIdx.y;
    int base = b * L_ + blockIdx.x * 256;
    float sc = g_scale[tid], sh = g_shift[tid];
    float acc = 0.f;
    for (int r = 0; r < 256; r++) {
        int row = base + r;
        if (mask[row]) {
            float v = fmaf(g_h[(size_t)row * H_ + tid], sc, sh);
            acc += fmaxf(v, 0.f);
        }
    }
    atomicAdd(&g_pooled[b * H_ + tid], acc);
}

// ---------------------------------------------------------------------------
// 6) tiny GEMM2: out[b] = (pooled[b]/cnt[b]) @ W2 + b2   (32x512x512)
// ---------------------------------------------------------------------------
__global__ __launch_bounds__(512) void k_gemm2(
    const float* __restrict__ W2,
    const float* __restrict__ b2,
    float* __restrict__ out)
{
    __shared__ float p[H_];
    int b = blockIdx.x;
    int j = threadIdx.x;
    float cnt = fmaxf(g_counts[b], 1.f);
    p[j] = g_pooled[b * H_ + j] / cnt;
    __syncthreads();
    float acc = b2[j];
    #pragma unroll 8
    for (int h = 0; h < H_; h++)
        acc = fmaf(p[h], W2[(size_t)h * H_ + j], acc);
    out[b * H_ + j] = acc;
}

// ---------------------------------------------------------------------------
extern "C" void kernel_launch(void* const* d_in, const int* in_sizes, int n_in,
                              void* d_out, int out_size) {
    const float* hidden = (const float*)d_in[0];
    const int*   mask   = (const int*)  d_in[1];
    const float* W1     = (const float*)d_in[2];
    const float* b1     = (const float*)d_in[3];
    const float* gamma  = (const float*)d_in[4];
    const float* beta   = (const float*)d_in[5];
    const float* W2     = (const float*)d_in[6];
    const float* b2     = (const float*)d_in[7];
    float* out = (float*)d_out;

    k_zero<<<64, 256>>>();
    k_counts<<<B_, 256>>>(mask);
    dim3 g1(H_ / BN, M_ / BM);         // (8, 512)
    k_gemm1<<<g1, 256>>>(hidden, W1, b1);
    k_stats<<<256, 256>>>(mask);
    k_finalize<<<1, 512>>>(gamma, beta);
    dim3 gp(8, B_);
    k_pool<<<gp, 512>>>(mask);
    k_gemm2<<<B_, 512>>>(W2, b2, out);
}

// round 4
// speedup vs baseline: 1.5198x; 1.5198x over previous
#include <cuda_runtime.h>
#include <cuda_bf16.h>
#include <cstdint>

#define B_ 32
#define L_ 2048
#define D_ 768
#define H_ 512
#define M_ (B_*L_)   // 65536 tokens

// ---- scratch (__device__ globals per allocation rules) ----
__device__ float g_h[(size_t)M_ * H_];          // 134 MB intermediate h
__device__ __nv_bfloat16 g_w1t_hi[H_ * D_];     // W1 transposed, bf16 hi
__device__ __nv_bfloat16 g_w1t_lo[H_ * D_];     // W1 transposed, bf16 lo
__device__ float g_sum[H_];
__device__ float g_sumsq[H_];
__device__ float g_scale[H_];
__device__ float g_shift[H_];
__device__ float g_counts[B_];
__device__ float g_pooled[B_ * H_];

// =====================================================================
// helpers
// =====================================================================
__device__ __forceinline__ void mma16816(float* c, const uint32_t* a,
                                         const uint32_t* b) {
    asm volatile(
        "mma.sync.aligned.m16n8k16.row.col.f32.bf16.bf16.f32 "
        "{%0,%1,%2,%3}, {%4,%5,%6,%7}, {%8,%9}, {%0,%1,%2,%3};"
        : "+f"(c[0]), "+f"(c[1]), "+f"(c[2]), "+f"(c[3])
        : "r"(a[0]), "r"(a[1]), "r"(a[2]), "r"(a[3]), "r"(b[0]), "r"(b[1]));
}

#define CP_ASYNC16(dst, src) \
    asm volatile("cp.async.ca.shared.global [%0], [%1], 16;" \
                 :: "r"(dst), "l"(src) : "memory")
#define CP_COMMIT()  asm volatile("cp.async.commit_group;" ::: "memory")
#define CP_WAIT0()   asm volatile("cp.async.wait_group 0;" ::: "memory")

__device__ __forceinline__ uint32_t smem_u32(const void* p) {
    uint32_t a;
    asm("{ .reg .u64 t; cvta.to.shared.u64 t, %1; cvt.u32.u64 %0, t; }"
        : "=r"(a) : "l"(p));
    return a;
}

__device__ __forceinline__ void cvt2(float x, float y, uint32_t& hi, uint32_t& lo) {
    __nv_bfloat16 hx = __float2bfloat16_rn(x);
    __nv_bfloat16 hy = __float2bfloat16_rn(y);
    float rx = x - __bfloat162float(hx);
    float ry = y - __bfloat162float(hy);
    __nv_bfloat16 lx = __float2bfloat16_rn(rx);
    __nv_bfloat16 ly = __float2bfloat16_rn(ry);
    hi = (uint32_t)__bfloat16_as_ushort(hx) | ((uint32_t)__bfloat16_as_ushort(hy) << 16);
    lo = (uint32_t)__bfloat16_as_ushort(lx) | ((uint32_t)__bfloat16_as_ushort(ly) << 16);
}

// =====================================================================
// 0) zero accumulators
// =====================================================================
__global__ void k_zero() {
    int i = blockIdx.x * blockDim.x + threadIdx.x;
    if (i < H_) { g_sum[i] = 0.f; g_sumsq[i] = 0.f; }
    if (i < B_ * H_) g_pooled[i] = 0.f;
}

// =====================================================================
// 1) per-batch valid-token counts
// =====================================================================
__global__ void k_counts(const int* __restrict__ mask) {
    __shared__ float red[256];
    int b = blockIdx.x;
    float s = 0.f;
    for (int l = threadIdx.x; l < L_; l += 256)
        s += (float)mask[b * L_ + l];
    red[threadIdx.x] = s;
    __syncthreads();
    for (int o = 128; o > 0; o >>= 1) {
        if (threadIdx.x < o) red[threadIdx.x] += red[threadIdx.x + o];
        __syncthreads();
    }
    if (threadIdx.x == 0) g_counts[b] = red[0];
}

// =====================================================================
// 1b) prep: W1 (D,H) -> transposed bf16 hi/lo (H,D)
// =====================================================================
__global__ void k_prepW1(const float* __restrict__ W1) {
    int idx = blockIdx.x * 256 + threadIdx.x;   // (n, k2) pairs
    if (idx >= H_ * (D_ / 2)) return;
    int n  = idx / (D_ / 2);
    int k2 = idx % (D_ / 2);
    float f0 = W1[(size_t)(2 * k2)     * H_ + n];
    float f1 = W1[(size_t)(2 * k2 + 1) * H_ + n];
    uint32_t ph, pl;
    cvt2(f0, f1, ph, pl);
    ((uint32_t*)g_w1t_hi)[idx] = ph;
    ((uint32_t*)g_w1t_lo)[idx] = pl;
}

// =====================================================================
// 2) GEMM1: h = hidden @ W1 + b1 via mma.sync bf16x3
//    CTA tile 128x128x32, 8 warps of 64x32, double-buffered SMEM
// =====================================================================
#define BKC 32
#define NCHUNK (D_ / BKC)       // 24
// SMEM per buffer (u32 units): AH 2560, AL 2560, BH 2560, BL 2560 = 10240
// (rows padded to 40 bf16 = 20 u32 per row)
#define BUF_U32 10240
#define SMEM_GEMM (2 * BUF_U32 * 4)   // 81920 bytes

__global__ __launch_bounds__(256, 1) void k_gemm_mma(
    const float* __restrict__ A,    // hidden (M x D)
    const float* __restrict__ b1)
{
    extern __shared__ uint32_t S[];
    const int tid  = threadIdx.x;
    const int lane = tid & 31;
    const int wid  = tid >> 5;
    const int warp_m = wid & 1;       // 0..1  -> 64 rows
    const int warp_n = wid >> 1;      // 0..3  -> 32 cols
    const int m0 = blockIdx.y * 128;
    const int n0 = blockIdx.x * 128;

    // loader mapping: 2 threads per row, each handles 16 cols
    const int lr = tid >> 1;          // 0..127
    const int lh = tid & 1;           // half

    const float4* aglob = (const float4*)(A + (size_t)(m0 + lr) * D_ + lh * 16);
    const __nv_bfloat16* bhg = g_w1t_hi + (size_t)(n0 + lr) * D_ + lh * 16;
    const __nv_bfloat16* blg = g_w1t_lo + (size_t)(n0 + lr) * D_ + lh * 16;

    // smem store offsets (u32 index): row lr, cols lh*16.. -> u32 lr*20 + lh*8
    const int stoff = lr * 20 + lh * 8;
    const uint32_t sbase = smem_u32(S);

    float c[4][4][4];
    #pragma unroll
    for (int i = 0; i < 4; i++)
        #pragma unroll
        for (int j = 0; j < 4; j++)
            #pragma unroll
            for (int q = 0; q < 4; q++) c[i][j][q] = 0.f;

    // ---- prologue: load chunk 0 into buffer 0 ----
    {
        // B via cp.async
        uint32_t bhdst = sbase + (5120 + stoff) * 4;
        uint32_t bldst = sbase + (7680 + stoff) * 4;
        CP_ASYNC16(bhdst,      bhg);
        CP_ASYNC16(bhdst + 16, bhg + 8);
        CP_ASYNC16(bldst,      blg);
        CP_ASYNC16(bldst + 16, blg + 8);
        CP_COMMIT();
        // A convert
        float4 a4[4];
        #pragma unroll
        for (int i = 0; i < 4; i++) a4[i] = aglob[i];
        uint32_t hu[8], lu[8];
        #pragma unroll
        for (int i = 0; i < 4; i++) {
            cvt2(a4[i].x, a4[i].y, hu[2*i],   lu[2*i]);
            cvt2(a4[i].z, a4[i].w, hu[2*i+1], lu[2*i+1]);
        }
        *(uint4*)&S[stoff]          = make_uint4(hu[0], hu[1], hu[2], hu[3]);
        *(uint4*)&S[stoff + 4]      = make_uint4(hu[4], hu[5], hu[6], hu[7]);
        *(uint4*)&S[2560 + stoff]     = make_uint4(lu[0], lu[1], lu[2], lu[3]);
        *(uint4*)&S[2560 + stoff + 4] = make_uint4(lu[4], lu[5], lu[6], lu[7]);
        CP_WAIT0();
    }
    __syncthreads();

    const int ar = warp_m * 64 + (lane >> 2);
    const int bn = warp_n * 32 + (lane >> 2);
    const int kq = lane & 3;

    for (int cidx = 0; cidx < NCHUNK; ++cidx) {
        const int cur = cidx & 1;
        const int nxt = cur ^ 1;
        float4 a4[4];
        if (cidx + 1 < NCHUNK) {
            const int kt = (cidx + 1) * BKC;
            // B prefetch via cp.async into nxt buffer
            uint32_t bhdst = sbase + (nxt * BUF_U32 + 5120 + stoff) * 4;
            uint32_t bldst = sbase + (nxt * BUF_U32 + 7680 + stoff) * 4;
            CP_ASYNC16(bhdst,      bhg + kt);
            CP_ASYNC16(bhdst + 16, bhg + kt + 8);
            CP_ASYNC16(bldst,      blg + kt);
            CP_ASYNC16(bldst + 16, blg + kt + 8);
            CP_COMMIT();
            // A prefetch into regs
            #pragma unroll
            for (int i = 0; i < 4; i++) a4[i] = aglob[(cidx + 1) * 8 + i];
        }

        // ---- compute on cur buffer ----
        {
            const uint32_t* AH = S  + cur * BUF_U32;
            const uint32_t* AL = AH + 2560;
            const uint32_t* BH = AH + 5120;
            const uint32_t* BL = AH + 7680;
            #pragma unroll
            for (int ks2 = 0; ks2 < 16; ks2 += 8) {     // k offset /2
                uint32_t ah[4][4], al[4][4], bh[4][2], bl[4][2];
                #pragma unroll
                for (int mi = 0; mi < 4; mi++) {
                    int base = (ar + mi * 16) * 20 + ks2 + kq;
                    ah[mi][0] = AH[base];       ah[mi][1] = AH[base + 160];
                    ah[mi][2] = AH[base + 4];   ah[mi][3] = AH[base + 164];
                    al[mi][0] = AL[base];       al[mi][1] = AL[base + 160];
                    al[mi][2] = AL[base + 4];   al[mi][3] = AL[base + 164];
                }
                #pragma unroll
                for (int ni = 0; ni < 4; ni++) {
                    int base = (bn + ni * 8) * 20 + ks2 + kq;
                    bh[ni][0] = BH[base];  bh[ni][1] = BH[base + 4];
                    bl[ni][0] = BL[base];  bl[ni][1] = BL[base + 4];
                }
                #pragma unroll
                for (int mi = 0; mi < 4; mi++)
                    #pragma unroll
                    for (int ni = 0; ni < 4; ni++) {
                        mma16816(c[mi][ni], ah[mi], bh[ni]);
                        mma16816(c[mi][ni], ah[mi], bl[ni]);
                        mma16816(c[mi][ni], al[mi], bh[ni]);
                    }
            }
        }

        if (cidx + 1 < NCHUNK) {
            // A convert+store into nxt buffer
            uint32_t hu[8], lu[8];
            #pragma unroll
            for (int i = 0; i < 4; i++) {
                cvt2(a4[i].x, a4[i].y, hu[2*i],   lu[2*i]);
                cvt2(a4[i].z, a4[i].w, hu[2*i+1], lu[2*i+1]);
            }
            uint32_t* AHn = S + nxt * BUF_U32;
            *(uint4*)&AHn[stoff]          = make_uint4(hu[0], hu[1], hu[2], hu[3]);
            *(uint4*)&AHn[stoff + 4]      = make_uint4(hu[4], hu[5], hu[6], hu[7]);
            *(uint4*)&AHn[2560 + stoff]     = make_uint4(lu[0], lu[1], lu[2], lu[3]);
            *(uint4*)&AHn[2560 + stoff + 4] = make_uint4(lu[4], lu[5], lu[6], lu[7]);
            CP_WAIT0();
        }
        __syncthreads();
    }

    // ---- epilogue: + b1, store h ----
    const int rbase = m0 + warp_m * 64 + (lane >> 2);
    const int cbase = n0 + warp_n * 32 + (lane & 3) * 2;
    #pragma unroll
    for (int ni = 0; ni < 4; ni++) {
        int col = cbase + ni * 8;
        float2 bb = *(const float2*)&b1[col];
        #pragma unroll
        for (int mi = 0; mi < 4; mi++) {
            int r0 = rbase + mi * 16;
            float2 o0, o1;
            o0.x = c[mi][ni][0] + bb.x;
            o0.y = c[mi][ni][1] + bb.y;
            o1.x = c[mi][ni][2] + bb.x;
            o1.y = c[mi][ni][3] + bb.y;
            *(float2*)&g_h[(size_t)r0 * H_ + col]       = o0;
            *(float2*)&g_h[(size_t)(r0 + 8) * H_ + col] = o1;
        }
    }
}

// =====================================================================
// 3) masked per-feature sum / sumsq over h
// =====================================================================
__global__ __launch_bounds__(256) void k_stats(const int* __restrict__ mask) {
    int tid = threadIdx.x;
    int r0 = blockIdx.x * 256;
    float s0 = 0.f, q0 = 0.f, s1 = 0.f, q1 = 0.f;
    for (int r = 0; r < 256; r++) {
        int row = r0 + r;
        if (mask[row]) {
            float v0 = g_h[(size_t)row * H_ + tid];
            float v1 = g_h[(size_t)row * H_ + tid + 256];
            s0 += v0; q0 += v0 * v0;
            s1 += v1; q1 += v1 * v1;
        }
    }
    atomicAdd(&g_sum[tid],         s0);
    atomicAdd(&g_sumsq[tid],       q0);
    atomicAdd(&g_sum[tid + 256],   s1);
    atomicAdd(&g_sumsq[tid + 256], q1);
}

// =====================================================================
// 4) finalize BN affine
// =====================================================================
__global__ void k_finalize(const float* __restrict__ gamma,
                           const float* __restrict__ beta) {
    int tid = threadIdx.x;   // 512 threads
    float nv = 0.f;
    #pragma unroll
    for (int b = 0; b < B_; b++) nv += g_counts[b];
    nv = fmaxf(nv, 1.f);
    float mean = g_sum[tid] / nv;
    float var  = g_sumsq[tid] / nv - mean * mean;
    var = fmaxf(var, 0.f);
    float istd = rsqrtf(var + 1e-5f);
    float sc = istd * gamma[tid];
    g_scale[tid] = sc;
    g_shift[tid] = beta[tid] - mean * sc;
}

// =====================================================================
// 5) masked relu-normalize-pool
// =====================================================================
__global__ __launch_bounds__(512) void k_pool(const int* __restrict__ mask) {
    int tid = threadIdx.x;       // feature
    int b = blockIdx.y;
    int base = b * L_ + blockIdx.x * 256;
    float sc = g_scale[tid], sh = g_shift[tid];
    float acc = 0.f;
    for (int r = 0; r < 256; r++) {
        int row = base + r;
        if (mask[row]) {
            float v = fmaf(g_h[(size_t)row * H_ + tid], sc, sh);
            acc += fmaxf(v, 0.f);
        }
    }
    atomicAdd(&g_pooled[b * H_ + tid], acc);
}

// =====================================================================
// 6) tiny GEMM2
// =====================================================================
__global__ __launch_bounds__(512) void k_gemm2(
    const float* __restrict__ W2,
    const float* __restrict__ b2,
    float* __restrict__ out)
{
    __shared__ float p[H_];
    int b = blockIdx.x;
    int j = threadIdx.x;
    float cnt = fmaxf(g_counts[b], 1.f);
    p[j] = g_pooled[b * H_ + j] / cnt;
    __syncthreads();
    float acc = b2[j];
    #pragma unroll 8
    for (int h = 0; h < H_; h++)
        acc = fmaf(p[h], W2[(size_t)h * H_ + j], acc);
    out[b * H_ + j] = acc;
}

// =====================================================================
extern "C" void kernel_launch(void* const* d_in, const int* in_sizes, int n_in,
                              void* d_out, int out_size) {
    const float* hidden = (const float*)d_in[0];
    const int*   mask   = (const int*)  d_in[1];
    const float* W1     = (const float*)d_in[2];
    const float* b1     = (const float*)d_in[3];
    const float* gamma  = (const float*)d_in[4];
    const float* beta   = (const float*)d_in[5];
    const float* W2     = (const float*)d_in[6];
    const float* b2     = (const float*)d_in[7];
    float* out = (float*)d_out;

    cudaFuncSetAttribute(k_gemm_mma,
                         cudaFuncAttributeMaxDynamicSharedMemorySize, SMEM_GEMM);

    k_zero<<<64, 256>>>();
    k_counts<<<B_, 256>>>(mask);
    k_prepW1<<<(H_ * (D_ / 2) + 255) / 256, 256>>>(W1);
    dim3 g1(H_ / 128, M_ / 128);                 // (4, 512)
    k_gemm_mma<<<g1, 256, SMEM_GEMM>>>(hidden, b1);
    k_stats<<<256, 256>>>(mask);
    k_finalize<<<1, 512>>>(gamma, beta);
    dim3 gp(8, B_);
    k_pool<<<gp, 512>>>(mask);
    k_gemm2<<<B_, 512>>>(W2, b2, out);
}

// round 6
// speedup vs baseline: 1.7718x; 1.1658x over previous
#include <cuda_runtime.h>
#include <cuda_bf16.h>
#include <cstdint>

#define B_ 32
#define L_ 2048
#define D_ 768
#define H_ 512
#define M_ (B_*L_)   // 65536 tokens

// ---- scratch (__device__ globals per allocation rules) ----
__device__ float g_h[(size_t)M_ * H_];          // 134 MB intermediate h
__device__ __nv_bfloat16 g_w1t_hi[H_ * D_];     // W1 transposed, bf16 hi
__device__ __nv_bfloat16 g_w1t_lo[H_ * D_];     // W1 transposed, bf16 lo
__device__ float g_sum[H_];
__device__ float g_sumsq[H_];
__device__ float g_scale[H_];
__device__ float g_shift[H_];
__device__ float g_counts[B_];
__device__ float g_pooled[B_ * H_];

// =====================================================================
// helpers
// =====================================================================
__device__ __forceinline__ void mma16816(float* c, const uint32_t* a,
                                         const uint32_t* b) {
    asm volatile(
        "mma.sync.aligned.m16n8k16.row.col.f32.bf16.bf16.f32 "
        "{%0,%1,%2,%3}, {%4,%5,%6,%7}, {%8,%9}, {%0,%1,%2,%3};"
        : "+f"(c[0]), "+f"(c[1]), "+f"(c[2]), "+f"(c[3])
        : "r"(a[0]), "r"(a[1]), "r"(a[2]), "r"(a[3]), "r"(b[0]), "r"(b[1]));
}

__device__ __forceinline__ void ldsm4(uint32_t* r, uint32_t addr) {
    asm volatile("ldmatrix.sync.aligned.m8n8.x4.shared.b16 {%0,%1,%2,%3}, [%4];"
        : "=r"(r[0]), "=r"(r[1]), "=r"(r[2]), "=r"(r[3]) : "r"(addr));
}

#define CP_ASYNC16(dst, src) \
    asm volatile("cp.async.ca.shared.global [%0], [%1], 16;" \
                 :: "r"(dst), "l"(src) : "memory")
#define CP_COMMIT()  asm volatile("cp.async.commit_group;" ::: "memory")
#define CP_WAIT0()   asm volatile("cp.async.wait_group 0;" ::: "memory")

__device__ __forceinline__ uint32_t smem_u32(const void* p) {
    uint32_t a;
    asm("{ .reg .u64 t; cvta.to.shared.u64 t, %1; cvt.u32.u64 %0, t; }"
        : "=r"(a) : "l"(p));
    return a;
}

__device__ __forceinline__ void cvt2(float x, float y, uint32_t& hi, uint32_t& lo) {
    __nv_bfloat16 hx = __float2bfloat16_rn(x);
    __nv_bfloat16 hy = __float2bfloat16_rn(y);
    float rx = x - __bfloat162float(hx);
    float ry = y - __bfloat162float(hy);
    __nv_bfloat16 lx = __float2bfloat16_rn(rx);
    __nv_bfloat16 ly = __float2bfloat16_rn(ry);
    hi = (uint32_t)__bfloat16_as_ushort(hx) | ((uint32_t)__bfloat16_as_ushort(hy) << 16);
    lo = (uint32_t)__bfloat16_as_ushort(lx) | ((uint32_t)__bfloat16_as_ushort(ly) << 16);
}

// =====================================================================
// 0) zero accumulators
// =====================================================================
__global__ void k_zero() {
    int i = blockIdx.x * blockDim.x + threadIdx.x;
    if (i < H_) { g_sum[i] = 0.f; g_sumsq[i] = 0.f; }
    if (i < B_ * H_) g_pooled[i] = 0.f;
}

// =====================================================================
// 1) per-batch valid-token counts
// =====================================================================
__global__ void k_counts(const int* __restrict__ mask) {
    __shared__ float red[256];
    int b = blockIdx.x;
    float s = 0.f;
    for (int l = threadIdx.x; l < L_; l += 256)
        s += (float)mask[b * L_ + l];
    red[threadIdx.x] = s;
    __syncthreads();
    for (int o = 128; o > 0; o >>= 1) {
        if (threadIdx.x < o) red[threadIdx.x] += red[threadIdx.x + o];
        __syncthreads();
    }
    if (threadIdx.x == 0) g_counts[b] = red[0];
}

// =====================================================================
// 1b) prep: W1 (D,H) -> transposed bf16 hi/lo (H,D)
// =====================================================================
__global__ void k_prepW1(const float* __restrict__ W1) {
    int idx = blockIdx.x * 256 + threadIdx.x;   // (n, k2) pairs
    if (idx >= H_ * (D_ / 2)) return;
    int n  = idx / (D_ / 2);
    int k2 = idx % (D_ / 2);
    float f0 = W1[(size_t)(2 * k2)     * H_ + n];
    float f1 = W1[(size_t)(2 * k2 + 1) * H_ + n];
    uint32_t ph, pl;
    cvt2(f0, f1, ph, pl);
    ((uint32_t*)g_w1t_hi)[idx] = ph;
    ((uint32_t*)g_w1t_lo)[idx] = pl;
}

// =====================================================================
// 2) GEMM1: h = hidden @ W1 + b1 via mma.sync bf16x3 + ldmatrix
//    CTA tile 128x128x32, 512 threads, 16 warps of 32x32, dbl-buffered
// =====================================================================
#define BKC 32
#define NCHUNK (D_ / BKC)       // 24
// SMEM per buffer: rows padded to 40 bf16 (80 B = 20 u32)
// AH 128*80=10240 B, AL, BH, BL  -> 40960 B per buffer
#define BUFB   40960
#define ALOFF  10240
#define BHOFF  20480
#define BLOFF  30720
#define SMEM_GEMM (2 * BUFB)    // 81920 bytes

__global__ __launch_bounds__(512, 1) void k_gemm_mma(
    const float* __restrict__ A,    // hidden (M x D)
    const float* __restrict__ b1)
{
    extern __shared__ uint32_t S[];
    const uint32_t sbase = smem_u32(S);
    const int tid  = threadIdx.x;
    const int lane = tid & 31;
    const int wid  = tid >> 5;        // 0..15
    const int warp_m = wid & 3;       // 4 m-groups of 32 rows
    const int warp_n = wid >> 2;      // 4 n-groups of 32 cols
    const int m0 = blockIdx.y * 128;
    const int n0 = blockIdx.x * 128;

    // loader mapping: 4 threads per row, each 8 elements
    const int lr = tid >> 2;          // 0..127
    const int lq = tid & 3;           // 8-element group

    const float4* aglob = (const float4*)(A + (size_t)(m0 + lr) * D_) + lq * 2;
    const __nv_bfloat16* bhg = g_w1t_hi + (size_t)(n0 + lr) * D_ + lq * 8;
    const __nv_bfloat16* blg = g_w1t_lo + (size_t)(n0 + lr) * D_ + lq * 8;
    const uint32_t stoff = lr * 80 + lq * 16;           // byte offset in tile

    // fragment ldmatrix base offsets (bytes)
    const uint32_t aoff = (uint32_t)(warp_m * 32 + (lane & 15)) * 80 + ((lane >> 4) << 4);
    const uint32_t boff = BHOFF + (uint32_t)(warp_n * 32 + lane) * 80;

    float c[2][4][4];
    #pragma unroll
    for (int i = 0; i < 2; i++)
        #pragma unroll
        for (int j = 0; j < 4; j++)
            #pragma unroll
            for (int q = 0; q < 4; q++) c[i][j][q] = 0.f;

    // ---- prologue: load chunk 0 into buffer 0 ----
    {
        CP_ASYNC16(sbase + BHOFF + stoff, bhg);
        CP_ASYNC16(sbase + BLOFF + stoff, blg);
        CP_COMMIT();
        float4 a40 = aglob[0], a41 = aglob[1];
        uint32_t hu[4], lu[4];
        cvt2(a40.x, a40.y, hu[0], lu[0]);
        cvt2(a40.z, a40.w, hu[1], lu[1]);
        cvt2(a41.x, a41.y, hu[2], lu[2]);
        cvt2(a41.z, a41.w, hu[3], lu[3]);
        *(uint4*)((char*)S + stoff)         = make_uint4(hu[0], hu[1], hu[2], hu[3]);
        *(uint4*)((char*)S + ALOFF + stoff) = make_uint4(lu[0], lu[1], lu[2], lu[3]);
        CP_WAIT0();
    }
    __syncthreads();

    for (int cidx = 0; cidx < NCHUNK; ++cidx) {
        const int cur = cidx & 1;
        const int nxt = cur ^ 1;
        float4 a40, a41;
        if (cidx + 1 < NCHUNK) {
            const int kt = (cidx + 1) * BKC;
            CP_ASYNC16(sbase + nxt * BUFB + BHOFF + stoff, bhg + kt);
            CP_ASYNC16(sbase + nxt * BUFB + BLOFF + stoff, blg + kt);
            CP_COMMIT();
            a40 = aglob[(cidx + 1) * 8];
            a41 = aglob[(cidx + 1) * 8 + 1];
        }

        // ---- compute on cur buffer ----
        {
            const uint32_t bufb = sbase + cur * BUFB;
            #pragma unroll
            for (int ks = 0; ks < 2; ++ks) {            // two k16 groups
                const uint32_t kb = ks * 32;
                uint32_t ah[2][4], al[2][4];
                uint32_t bh0[4], bh1[4], bl0[4], bl1[4];
                #pragma unroll
                for (int mi = 0; mi < 2; mi++) {
                    ldsm4(ah[mi], bufb + aoff + mi * 16 * 80 + kb);
                    ldsm4(al[mi], bufb + ALOFF + aoff + mi * 16 * 80 + kb);
                }
                ldsm4(bh0, bufb + boff + kb);
                ldsm4(bh1, bufb + boff + kb + 16);
                ldsm4(bl0, bufb + (BLOFF - BHOFF) + boff + kb);
                ldsm4(bl1, bufb + (BLOFF - BHOFF) + boff + kb + 16);
                #pragma unroll
                for (int mi = 0; mi < 2; mi++)
                    #pragma unroll
                    for (int ni = 0; ni < 4; ni++) {
                        uint32_t bfh[2] = { bh0[ni], bh1[ni] };
                        uint32_t bfl[2] = { bl0[ni], bl1[ni] };
                        mma16816(c[mi][ni], ah[mi], bfh);
                        mma16816(c[mi][ni], ah[mi], bfl);
                        mma16816(c[mi][ni], al[mi], bfh);
                    }
            }
        }

        if (cidx + 1 < NCHUNK) {
            uint32_t hu[4], lu[4];
            cvt2(a40.x, a40.y, hu[0], lu[0]);
            cvt2(a40.z, a40.w, hu[1], lu[1]);
            cvt2(a41.x, a41.y, hu[2], lu[2]);
            cvt2(a41.z, a41.w, hu[3], lu[3]);
            char* bb = (char*)S + nxt * BUFB;
            *(uint4*)(bb + stoff)         = make_uint4(hu[0], hu[1], hu[2], hu[3]);
            *(uint4*)(bb + ALOFF + stoff) = make_uint4(lu[0], lu[1], lu[2], lu[3]);
            CP_WAIT0();
        }
        __syncthreads();
    }

    // ---- epilogue: + b1, store h ----
    const int rbase = m0 + warp_m * 32 + (lane >> 2);
    const int cbase = n0 + warp_n * 32 + (lane & 3) * 2;
    #pragma unroll
    for (int ni = 0; ni < 4; ni++) {
        int col = cbase + ni * 8;
        float2 bb = *(const float2*)&b1[col];
        #pragma unroll
        for (int mi = 0; mi < 2; mi++) {
            int r0 = rbase + mi * 16;
            float2 o0, o1;
            o0.x = c[mi][ni][0] + bb.x;
            o0.y = c[mi][ni][1] + bb.y;
            o1.x = c[mi][ni][2] + bb.x;
            o1.y = c[mi][ni][3] + bb.y;
            *(float2*)&g_h[(size_t)r0 * H_ + col]       = o0;
            *(float2*)&g_h[(size_t)(r0 + 8) * H_ + col] = o1;
        }
    }
}

// =====================================================================
// 3) masked per-feature sum / sumsq over h (float4, 512 blocks x 128 rows)
// =====================================================================
__global__ __launch_bounds__(128) void k_stats(const int* __restrict__ mask) {
    int tid = threadIdx.x;               // float4 feature group 0..127
    int r0 = blockIdx.x * 128;
    float4 s = make_float4(0.f, 0.f, 0.f, 0.f);
    float4 q = make_float4(0.f, 0.f, 0.f, 0.f);
    const float4* hp = (const float4*)g_h;
    #pragma unroll 4
    for (int r = 0; r < 128; r++) {
        int row = r0 + r;
        if (mask[row]) {
            float4 v = hp[(size_t)row * 128 + tid];
            s.x += v.x; q.x += v.x * v.x;
            s.y += v.y; q.y += v.y * v.y;
            s.z += v.z; q.z += v.z * v.z;
            s.w += v.w; q.w += v.w * v.w;
        }
    }
    int f = tid * 4;
    atomicAdd(&g_sum[f + 0], s.x);  atomicAdd(&g_sumsq[f + 0], q.x);
    atomicAdd(&g_sum[f + 1], s.y);  atomicAdd(&g_sumsq[f + 1], q.y);
    atomicAdd(&g_sum[f + 2], s.z);  atomicAdd(&g_sumsq[f + 2], q.z);
    atomicAdd(&g_sum[f + 3], s.w);  atomicAdd(&g_sumsq[f + 3], q.w);
}

// =====================================================================
// 4) finalize BN affine
// =====================================================================
__global__ void k_finalize(const float* __restrict__ gamma,
                           const float* __restrict__ beta) {
    int tid = threadIdx.x;   // 512 threads
    float nv = 0.f;
    #pragma unroll
    for (int b = 0; b < B_; b++) nv += g_counts[b];
    nv = fmaxf(nv, 1.f);
    float mean = g_sum[tid] / nv;
    float var  = g_sumsq[tid] / nv - mean * mean;
    var = fmaxf(var, 0.f);
    float istd = rsqrtf(var + 1e-5f);
    float sc = istd * gamma[tid];
    g_scale[tid] = sc;
    g_shift[tid] = beta[tid] - mean * sc;
}

// =====================================================================
// 5) masked relu-normalize-pool (float4)
// =====================================================================
__global__ __launch_bounds__(128) void k_pool(const int* __restrict__ mask) {
    int tid = threadIdx.x;               // float4 feature group
    int b = blockIdx.y;
    int base = b * L_ + blockIdx.x * 256;
    float4 sc = ((const float4*)g_scale)[tid];
    float4 sh = ((const float4*)g_shift)[tid];
    float4 acc = make_float4(0.f, 0.f, 0.f, 0.f);
    const float4* hp = (const float4*)g_h;
    #pragma unroll 4
    for (int r = 0; r < 256; r++) {
        int row = base + r;
        if (mask[row]) {
            float4 v = hp[(size_t)row * 128 + tid];
            acc.x += fmaxf(fmaf(v.x, sc.x, sh.x), 0.f);
            acc.y += fmaxf(fmaf(v.y, sc.y, sh.y), 0.f);
            acc.z += fmaxf(fmaf(v.z, sc.z, sh.z), 0.f);
            acc.w += fmaxf(fmaf(v.w, sc.w, sh.w), 0.f);
        }
    }
    int f = b * H_ + tid * 4;
    atomicAdd(&g_pooled[f + 0], acc.x);
    atomicAdd(&g_pooled[f + 1], acc.y);
    atomicAdd(&g_pooled[f + 2], acc.z);
    atomicAdd(&g_pooled[f + 3], acc.w);
}

// =====================================================================
// 6) tiny GEMM2
// =====================================================================
__global__ __launch_bounds__(512) void k_gemm2(
    const float* __restrict__ W2,
    const float* __restrict__ b2,
    float* __restrict__ out)
{
    __shared__ float p[H_];
    int b = blockIdx.x;
    int j = threadIdx.x;
    float cnt = fmaxf(g_counts[b], 1.f);
    p[j] = g_pooled[b * H_ + j] / cnt;
    __syncthreads();
    float acc = b2[j];
    #pragma unroll 8
    for (int h = 0; h < H_; h++)
        acc = fmaf(p[h], W2[(size_t)h * H_ + j], acc);
    out[b * H_ + j] = acc;
}

// =====================================================================
extern "C" void kernel_launch(void* const* d_in, const int* in_sizes, int n_in,
                              void* d_out, int out_size) {
    const float* hidden = (const float*)d_in[0];
    const int*   mask   = (const int*)  d_in[1];
    const float* W1     = (const float*)d_in[2];
    const float* b1     = (const float*)d_in[3];
    const float* gamma  = (const float*)d_in[4];
    const float* beta   = (const float*)d_in[5];
    const float* W2     = (const float*)d_in[6];
    const float* b2     = (const float*)d_in[7];
    float* out = (float*)d_out;

    cudaFuncSetAttribute(k_gemm_mma,
                         cudaFuncAttributeMaxDynamicSharedMemorySize, SMEM_GEMM);

    k_zero<<<64, 256>>>();
    k_counts<<<B_, 256>>>(mask);
    k_prepW1<<<(H_ * (D_ / 2) + 255) / 256, 256>>>(W1);
    dim3 g1(H_ / 128, M_ / 128);                 // (4, 512)
    k_gemm_mma<<<g1, 512, SMEM_GEMM>>>(hidden, b1);
    k_stats<<<512, 128>>>(mask);
    k_finalize<<<1, 512>>>(gamma, beta);
    dim3 gp(8, B_);
    k_pool<<<gp, 128>>>(mask);
    k_gemm2<<<B_, 512>>>(W2, b2, out);
}